// round 12
// baseline (speedup 1.0000x reference)
#include <cuda_runtime.h>
#include <cuda_fp16.h>
#include <cstdint>

#define TOKENS (8*2048)
#define EDIM 512

// Scratch: permuted attention output in fp16, W in fp16.
__device__ __half g_y[(size_t)TOKENS * EDIM];   // 16 MB
__device__ __half g_W[EDIM * EDIM];             // 512 KB

// ============================ helpers ======================================
__device__ __forceinline__ float ex2(float x) {
    float r; asm("ex2.approx.f32 %0, %1;" : "=f"(r) : "f"(x)); return r;
}
__device__ __forceinline__ uint32_t f22h2(float a, float b) {
    __half2 h = __floats2half2_rn(a, b);
    return *(uint32_t*)&h;
}
__device__ __forceinline__ float2 h2f2(uint32_t u) {
    return __half22float2(*(__half2*)&u);
}
__device__ __forceinline__ uint32_t smem_u32(const void* p) {
    uint32_t a;
    asm("{ .reg .u64 t; cvta.to.shared.u64 t, %1; cvt.u32.u64 %0, t; }" : "=r"(a) : "l"(p));
    return a;
}
__device__ __forceinline__ uint32_t movm(uint32_t s) {
    uint32_t d;
    asm volatile("movmatrix.sync.aligned.m8n8.trans.b16 %0, %1;" : "=r"(d) : "r"(s));
    return d;
}
__device__ __forceinline__ void mma_16n8k8(float* c, uint32_t a0, uint32_t a1, uint32_t b0) {
    asm volatile(
        "mma.sync.aligned.m16n8k8.row.col.f32.f16.f16.f32 "
        "{%0,%1,%2,%3}, {%4,%5}, {%6}, {%0,%1,%2,%3};"
        : "+f"(c[0]), "+f"(c[1]), "+f"(c[2]), "+f"(c[3])
        : "r"(a0), "r"(a1), "r"(b0));
}
__device__ __forceinline__ void mma_16n8k16(float* c, const uint32_t* a,
                                            uint32_t b0, uint32_t b1) {
    asm volatile(
        "mma.sync.aligned.m16n8k16.row.col.f32.f16.f16.f32 "
        "{%0,%1,%2,%3}, {%4,%5,%6,%7}, {%8,%9}, {%0,%1,%2,%3};"
        : "+f"(c[0]), "+f"(c[1]), "+f"(c[2]), "+f"(c[3])
        : "r"(a[0]), "r"(a[1]), "r"(a[2]), "r"(a[3]), "r"(b0), "r"(b1));
}
__device__ __forceinline__ void ldsm_x4(uint32_t* r, uint32_t addr) {
    asm volatile("ldmatrix.sync.aligned.m8n8.x4.shared.b16 {%0,%1,%2,%3}, [%4];"
        : "=r"(r[0]), "=r"(r[1]), "=r"(r[2]), "=r"(r[3]) : "r"(addr));
}
__device__ __forceinline__ void cp16(uint32_t saddr, const void* gptr) {
    asm volatile("cp.async.cg.shared.global [%0], [%1], 16;" :: "r"(saddr), "l"(gptr));
}
#define CP_COMMIT()  asm volatile("cp.async.commit_group;" ::: "memory")
#define CP_WAIT(n)   asm volatile("cp.async.wait_group %0;" :: "n"(n) : "memory")
#define SW128(o) ((o) ^ (((o) >> 3) & 0x70))
#define TRI(a, b) ((a) * ((a) - 1) / 2 + (b))     // a > b

// ---------------------------------------------------------------------------
// K1: per-token quantum attention (R11 symmetric-exp body) over one chunk.
// ---------------------------------------------------------------------------
__global__ __launch_bounds__(256) void attn_kernel(const float* __restrict__ x,
                                                   const float* __restrict__ theta,
                                                   const float* __restrict__ W,
                                                   int tokBase, int doConv) {
    if (doConv && blockIdx.x < 128) {   // W fp16 convert (chunk 0 only)
        int t = blockIdx.x * 256 + threadIdx.x;
        float4 aq = *(const float4*)&W[(size_t)t * 8];
        float4 bq = *(const float4*)&W[(size_t)t * 8 + 4];
        __half2 h[4] = {__floats2half2_rn(aq.x, aq.y), __floats2half2_rn(aq.z, aq.w),
                        __floats2half2_rn(bq.x, bq.y), __floats2half2_rn(bq.z, bq.w)};
        *(uint4*)&g_W[(size_t)t * 8] = *(uint4*)h;
    }

    __shared__ __half sproj[8][512];        // [warp][h*8+d]
    __shared__ __half sprojT[8][8][72];     // [warp][d][h], pitch 72 halfs

    const int warp = threadIdx.x >> 5;
    const int lane = threadIdx.x & 31;
    const int token = tokBase + blockIdx.x * 8 + warp;
    const float* xt = x + (size_t)token * EDIM;

    const float tv = __ldg(&theta[lane & 7]);
    #pragma unroll
    for (int i = 0; i < 16; i++) {
        int idx = lane + 32 * i;
        __half c = __float2half(__cosf(xt[idx] + tv));
        sproj[warp][idx] = c;
        sprojT[warp][idx & 7][idx >> 3] = c;
    }
    __syncwarp();

    const int q  = lane >> 2;
    const int r2 = (lane & 3) * 2;
    const float C2 = 0.51006973f;    // log2(e)/sqrt(8)

    uint32_t aA[4][2];
    #pragma unroll
    for (int mi = 0; mi < 4; mi++) {
        float2 lo = h2f2(*(const uint32_t*)&sproj[warp][(16 * mi + q) * 8 + r2]);
        float2 hi = h2f2(*(const uint32_t*)&sproj[warp][(16 * mi + q + 8) * 8 + r2]);
        aA[mi][0] = f22h2(lo.x * C2, lo.y * C2);
        aA[mi][1] = f22h2(hi.x * C2, hi.y * C2);
    }

    float o[4][4];
    float lsl[4], lsh[4];
    #pragma unroll
    for (int mi = 0; mi < 4; mi++) {
        o[mi][0] = o[mi][1] = o[mi][2] = o[mi][3] = 0.f;
        lsl[mi] = lsh[mi] = 0.f;
    }

    uint32_t Psrc[28];      // retained lower-tri halves E(a,b), a>b

    #pragma unroll
    for (int nj = 0; nj < 8; nj++) {
        uint32_t bS = *(const uint32_t*)&sproj[warp][(8 * nj + q) * 8 + r2];
        uint32_t bO = *(const uint32_t*)&sprojT[warp][q][8 * nj + r2];
        uint32_t eh[8];

        #pragma unroll
        for (int a = 0; a < nj; a++) {
            eh[a] = movm(Psrc[TRI(nj, a)]);
            float2 f = h2f2(eh[a]);
            if (a & 1) lsh[a >> 1] += f.x + f.y;
            else       lsl[a >> 1] += f.x + f.y;
        }
        #pragma unroll
        for (int mi = 0; mi < 4; mi++) {
            if (mi >= (nj >> 1)) {
                float c[4] = {0.f, 0.f, 0.f, 0.f};
                mma_16n8k8(c, aA[mi][0], aA[mi][1], bS);
                const int a0 = 2 * mi, a1 = 2 * mi + 1;
                if (a0 >= nj) {
                    float p0 = ex2(c[0]), p1 = ex2(c[1]);
                    lsl[mi] += p0 + p1;
                    eh[a0] = f22h2(p0, p1);
                    if (a0 > nj) Psrc[TRI(a0, nj)] = eh[a0];
                }
                {
                    float p2 = ex2(c[2]), p3 = ex2(c[3]);
                    lsh[mi] += p2 + p3;
                    eh[a1] = f22h2(p2, p3);
                    if (a1 > nj) Psrc[TRI(a1, nj)] = eh[a1];
                }
            }
        }
        #pragma unroll
        for (int mi = 0; mi < 4; mi++)
            mma_16n8k8(o[mi], eh[2 * mi], eh[2 * mi + 1], bO);
    }

    #pragma unroll
    for (int mi = 0; mi < 4; mi++) {
        lsl[mi] += __shfl_xor_sync(0xffffffffu, lsl[mi], 1);
        lsl[mi] += __shfl_xor_sync(0xffffffffu, lsl[mi], 2);
        lsh[mi] += __shfl_xor_sync(0xffffffffu, lsh[mi], 1);
        lsh[mi] += __shfl_xor_sync(0xffffffffu, lsh[mi], 2);
    }

    const int b = token >> 11;
    const int s = token & 2047;
    const size_t base = ((size_t)b * 2048 + (s >> 6)) * EDIM + (size_t)(s & 63) * 8;

    #pragma unroll
    for (int mi = 0; mi < 4; mi++) {
        float rl = __frcp_rn(lsl[mi]);
        float rh = __frcp_rn(lsh[mi]);
        int h0 = 16 * mi + q;
        __half2 v0 = __floats2half2_rn(o[mi][0] * rl, o[mi][1] * rl);
        *(__half2*)&g_y[base + (size_t)h0 * 32 * EDIM + r2] = v0;
        __half2 v1 = __floats2half2_rn(o[mi][2] * rh, o[mi][3] * rh);
        *(__half2*)&g_y[base + (size_t)(h0 + 8) * 32 * EDIM + r2] = v1;
    }
}

// ---------------------------------------------------------------------------
// K2: out = y @ W^T + bias over one chunk of M rows (R6/R11 body).
// ---------------------------------------------------------------------------
#define STAGE_BYTES 32768            // 16KB A + 16KB B per stage
#define GEMM_SMEM   65536

__global__ __launch_bounds__(256) void gemm_kernel(const float* __restrict__ bias,
                                                   float* __restrict__ out,
                                                   int mBase) {
    extern __shared__ __align__(1024) char smem[];
    const uint32_t sb = smem_u32(smem);
    const int tid  = threadIdx.x;
    const int warp = tid >> 5;
    const int lane = tid & 31;
    const int wm   = warp >> 2;      // 0..1
    const int wn   = warp & 3;       // 0..3
    const int blockM = mBase + blockIdx.x * 128;
    const int blockN = blockIdx.y * 128;

    const int lrow = tid >> 3;            // 0..31
    const int lcb  = (tid & 7) * 16;      // byte col in 128B row

    auto load_stage = [&](int s) {
        const int kt = s * 64;
        const uint32_t base = sb + (s & 1) * STAGE_BYTES;
        #pragma unroll
        for (int i = 0; i < 4; i++) {
            int row = lrow + i * 32;
            uint32_t o = SW128(row * 128 + lcb);
            cp16(base + o, &g_y[(size_t)(blockM + row) * 512 + kt + (lcb >> 1)]);
            cp16(base + 16384 + o, &g_W[(size_t)(blockN + row) * 512 + kt + (lcb >> 1)]);
        }
        CP_COMMIT();
    };

    float c[4][4][4];
    #pragma unroll
    for (int mi = 0; mi < 4; mi++)
        #pragma unroll
        for (int nj = 0; nj < 4; nj++)
            c[mi][nj][0] = c[mi][nj][1] = c[mi][nj][2] = c[mi][nj][3] = 0.f;

    load_stage(0);

    const int t  = lane & 15;
    const int hh = (lane >> 4) * 16;

    #pragma unroll 1
    for (int s = 0; s < 8; s++) {
        if (s + 1 < 8) { load_stage(s + 1); CP_WAIT(1); }
        else           { CP_WAIT(0); }
        __syncthreads();

        const uint32_t abase = sb + (s & 1) * STAGE_BYTES;
        const uint32_t bbase = abase + 16384;

        #pragma unroll
        for (int ks = 0; ks < 4; ks++) {
            uint32_t ra[4][4], rb[2][4];
            #pragma unroll
            for (int mi = 0; mi < 4; mi++) {
                uint32_t o = (wm * 64 + mi * 16 + t) * 128 + ks * 32 + hh;
                ldsm_x4(ra[mi], abase + SW128(o));
            }
            #pragma unroll
            for (int g = 0; g < 2; g++) {
                uint32_t o = (wn * 32 + g * 16 + t) * 128 + ks * 32 + hh;
                ldsm_x4(rb[g], bbase + SW128(o));   // non-trans: rows = n, k contiguous
            }
            #pragma unroll
            for (int mi = 0; mi < 4; mi++)
                #pragma unroll
                for (int nj = 0; nj < 4; nj++)
                    mma_16n8k16(c[mi][nj], ra[mi],
                                rb[nj >> 1][nj & 1], rb[nj >> 1][2 + (nj & 1)]);
        }
        __syncthreads();
    }

    const int q  = lane >> 2;
    const int r2 = (lane & 3) * 2;
    #pragma unroll
    for (int nj = 0; nj < 4; nj++) {
        const int col = blockN + wn * 32 + nj * 8 + r2;
        const float2 bv = *(const float2*)&bias[col];
        #pragma unroll
        for (int mi = 0; mi < 4; mi++) {
            const int row = blockM + wm * 64 + mi * 16 + q;
            float2 v0 = {c[mi][nj][0] + bv.x, c[mi][nj][1] + bv.y};
            float2 v1 = {c[mi][nj][2] + bv.x, c[mi][nj][3] + bv.y};
            *(float2*)&out[(size_t)row * 512 + col] = v0;
            *(float2*)&out[(size_t)(row + 8) * 512 + col] = v1;
        }
    }
}

// ---------------------------------------------------------------------------
// Stream/event pool, created at program load (before harness mem checkpoints).
// ---------------------------------------------------------------------------
struct StreamPool {
    cudaStream_t s2;
    cudaEvent_t evA[4];
    cudaEvent_t evG;
    StreamPool() {
        cudaStreamCreateWithFlags(&s2, cudaStreamNonBlocking);
        for (int i = 0; i < 4; i++)
            cudaEventCreateWithFlags(&evA[i], cudaEventDisableTiming);
        cudaEventCreateWithFlags(&evG, cudaEventDisableTiming);
    }
};
static StreamPool g_sp;

// ---------------------------------------------------------------------------
// 4 chunks x 2 batches; attn on default stream, gemm on s2 gated by events.
// gemm(chunk c) reads only g_y rows written by attn(chunk c); W converted in
// attn chunk 0 (before the first event fires).
// ---------------------------------------------------------------------------
extern "C" void kernel_launch(void* const* d_in, const int* in_sizes, int n_in,
                              void* d_out, int out_size) {
    const float* x     = (const float*)d_in[0];
    const float* theta = (const float*)d_in[1];
    const float* W     = (const float*)d_in[2];
    const float* bias  = (const float*)d_in[3];
    float* out = (float*)d_out;

    cudaFuncSetAttribute(gemm_kernel, cudaFuncAttributeMaxDynamicSharedMemorySize, GEMM_SMEM);

    for (int c = 0; c < 4; c++) {
        attn_kernel<<<512, 256, 0, 0>>>(x, theta, W, c * 4096, c == 0);
        cudaEventRecord(g_sp.evA[c], 0);
        cudaStreamWaitEvent(g_sp.s2, g_sp.evA[c], 0);
        gemm_kernel<<<dim3(32, 4), 256, GEMM_SMEM, g_sp.s2>>>(bias, out, c * 4096);
    }
    cudaEventRecord(g_sp.evG, g_sp.s2);
    cudaStreamWaitEvent(0, g_sp.evG, 0);
}

// round 13
// speedup vs baseline: 1.0059x; 1.0059x over previous
#include <cuda_runtime.h>
#include <cuda_fp16.h>
#include <cstdint>

#define TOKENS (8*2048)
#define EDIM 512

// Scratch: permuted attention output in fp16, W in fp16.
__device__ __half g_y[(size_t)TOKENS * EDIM];   // 16 MB
__device__ __half g_W[EDIM * EDIM];             // 512 KB

// ============================ helpers ======================================
__device__ __forceinline__ float ex2(float x) {
    float r; asm("ex2.approx.f32 %0, %1;" : "=f"(r) : "f"(x)); return r;
}
__device__ __forceinline__ uint32_t f22h2(float a, float b) {
    __half2 h = __floats2half2_rn(a, b);
    return *(uint32_t*)&h;
}
__device__ __forceinline__ float2 h2f2(uint32_t u) {
    return __half22float2(*(__half2*)&u);
}
__device__ __forceinline__ uint32_t smem_u32(const void* p) {
    uint32_t a;
    asm("{ .reg .u64 t; cvta.to.shared.u64 t, %1; cvt.u32.u64 %0, t; }" : "=r"(a) : "l"(p));
    return a;
}
__device__ __forceinline__ uint32_t movm(uint32_t s) {
    uint32_t d;
    asm volatile("movmatrix.sync.aligned.m8n8.trans.b16 %0, %1;" : "=r"(d) : "r"(s));
    return d;
}
__device__ __forceinline__ void mma_16n8k8(float* c, uint32_t a0, uint32_t a1, uint32_t b0) {
    asm volatile(
        "mma.sync.aligned.m16n8k8.row.col.f32.f16.f16.f32 "
        "{%0,%1,%2,%3}, {%4,%5}, {%6}, {%0,%1,%2,%3};"
        : "+f"(c[0]), "+f"(c[1]), "+f"(c[2]), "+f"(c[3])
        : "r"(a0), "r"(a1), "r"(b0));
}
__device__ __forceinline__ void mma_16n8k16(float* c, const uint32_t* a,
                                            uint32_t b0, uint32_t b1) {
    asm volatile(
        "mma.sync.aligned.m16n8k16.row.col.f32.f16.f16.f32 "
        "{%0,%1,%2,%3}, {%4,%5,%6,%7}, {%8,%9}, {%0,%1,%2,%3};"
        : "+f"(c[0]), "+f"(c[1]), "+f"(c[2]), "+f"(c[3])
        : "r"(a[0]), "r"(a[1]), "r"(a[2]), "r"(a[3]), "r"(b0), "r"(b1));
}
__device__ __forceinline__ void ldsm_x4(uint32_t* r, uint32_t addr) {
    asm volatile("ldmatrix.sync.aligned.m8n8.x4.shared.b16 {%0,%1,%2,%3}, [%4];"
        : "=r"(r[0]), "=r"(r[1]), "=r"(r[2]), "=r"(r[3]) : "r"(addr));
}
__device__ __forceinline__ void cp16(uint32_t saddr, const void* gptr) {
    asm volatile("cp.async.cg.shared.global [%0], [%1], 16;" :: "r"(saddr), "l"(gptr));
}
#define CP_COMMIT()  asm volatile("cp.async.commit_group;" ::: "memory")
#define CP_WAIT(n)   asm volatile("cp.async.wait_group %0;" :: "n"(n) : "memory")
#define SW128(o) ((o) ^ (((o) >> 3) & 0x70))
#define TRI(a, b) ((a) * ((a) - 1) / 2 + (b))     // a > b

// ---------------------------------------------------------------------------
// K1: per-token quantum attention (R11 symmetric-exp body) over one chunk.
// ---------------------------------------------------------------------------
__global__ __launch_bounds__(256) void attn_kernel(const float* __restrict__ x,
                                                   const float* __restrict__ theta,
                                                   const float* __restrict__ W,
                                                   int tokBase, int doConv) {
    if (doConv && blockIdx.x < 128) {   // W fp16 convert (chunk 0 only)
        int t = blockIdx.x * 256 + threadIdx.x;
        float4 aq = *(const float4*)&W[(size_t)t * 8];
        float4 bq = *(const float4*)&W[(size_t)t * 8 + 4];
        __half2 h[4] = {__floats2half2_rn(aq.x, aq.y), __floats2half2_rn(aq.z, aq.w),
                        __floats2half2_rn(bq.x, bq.y), __floats2half2_rn(bq.z, bq.w)};
        *(uint4*)&g_W[(size_t)t * 8] = *(uint4*)h;
    }

    __shared__ __half sproj[8][512];        // [warp][h*8+d]
    __shared__ __half sprojT[8][8][72];     // [warp][d][h], pitch 72 halfs

    const int warp = threadIdx.x >> 5;
    const int lane = threadIdx.x & 31;
    const int token = tokBase + blockIdx.x * 8 + warp;
    const float* xt = x + (size_t)token * EDIM;

    const float tv = __ldg(&theta[lane & 7]);
    #pragma unroll
    for (int i = 0; i < 16; i++) {
        int idx = lane + 32 * i;
        __half c = __float2half(__cosf(xt[idx] + tv));
        sproj[warp][idx] = c;
        sprojT[warp][idx & 7][idx >> 3] = c;
    }
    __syncwarp();

    const int q  = lane >> 2;
    const int r2 = (lane & 3) * 2;
    const float C2 = 0.51006973f;    // log2(e)/sqrt(8)

    uint32_t aA[4][2];
    #pragma unroll
    for (int mi = 0; mi < 4; mi++) {
        float2 lo = h2f2(*(const uint32_t*)&sproj[warp][(16 * mi + q) * 8 + r2]);
        float2 hi = h2f2(*(const uint32_t*)&sproj[warp][(16 * mi + q + 8) * 8 + r2]);
        aA[mi][0] = f22h2(lo.x * C2, lo.y * C2);
        aA[mi][1] = f22h2(hi.x * C2, hi.y * C2);
    }

    float o[4][4];
    float lsl[4], lsh[4];
    #pragma unroll
    for (int mi = 0; mi < 4; mi++) {
        o[mi][0] = o[mi][1] = o[mi][2] = o[mi][3] = 0.f;
        lsl[mi] = lsh[mi] = 0.f;
    }

    uint32_t Psrc[28];      // retained lower-tri halves E(a,b), a>b

    #pragma unroll
    for (int nj = 0; nj < 8; nj++) {
        uint32_t bS = *(const uint32_t*)&sproj[warp][(8 * nj + q) * 8 + r2];
        uint32_t bO = *(const uint32_t*)&sprojT[warp][q][8 * nj + r2];
        uint32_t eh[8];

        #pragma unroll
        for (int a = 0; a < nj; a++) {
            eh[a] = movm(Psrc[TRI(nj, a)]);
            float2 f = h2f2(eh[a]);
            if (a & 1) lsh[a >> 1] += f.x + f.y;
            else       lsl[a >> 1] += f.x + f.y;
        }
        #pragma unroll
        for (int mi = 0; mi < 4; mi++) {
            if (mi >= (nj >> 1)) {
                float c[4] = {0.f, 0.f, 0.f, 0.f};
                mma_16n8k8(c, aA[mi][0], aA[mi][1], bS);
                const int a0 = 2 * mi, a1 = 2 * mi + 1;
                if (a0 >= nj) {
                    float p0 = ex2(c[0]), p1 = ex2(c[1]);
                    lsl[mi] += p0 + p1;
                    eh[a0] = f22h2(p0, p1);
                    if (a0 > nj) Psrc[TRI(a0, nj)] = eh[a0];
                }
                {
                    float p2 = ex2(c[2]), p3 = ex2(c[3]);
                    lsh[mi] += p2 + p3;
                    eh[a1] = f22h2(p2, p3);
                    if (a1 > nj) Psrc[TRI(a1, nj)] = eh[a1];
                }
            }
        }
        #pragma unroll
        for (int mi = 0; mi < 4; mi++)
            mma_16n8k8(o[mi], eh[2 * mi], eh[2 * mi + 1], bO);
    }

    #pragma unroll
    for (int mi = 0; mi < 4; mi++) {
        lsl[mi] += __shfl_xor_sync(0xffffffffu, lsl[mi], 1);
        lsl[mi] += __shfl_xor_sync(0xffffffffu, lsl[mi], 2);
        lsh[mi] += __shfl_xor_sync(0xffffffffu, lsh[mi], 1);
        lsh[mi] += __shfl_xor_sync(0xffffffffu, lsh[mi], 2);
    }

    const int b = token >> 11;
    const int s = token & 2047;
    const size_t base = ((size_t)b * 2048 + (s >> 6)) * EDIM + (size_t)(s & 63) * 8;

    #pragma unroll
    for (int mi = 0; mi < 4; mi++) {
        float rl = __frcp_rn(lsl[mi]);
        float rh = __frcp_rn(lsh[mi]);
        int h0 = 16 * mi + q;
        __half2 v0 = __floats2half2_rn(o[mi][0] * rl, o[mi][1] * rl);
        *(__half2*)&g_y[base + (size_t)h0 * 32 * EDIM + r2] = v0;
        __half2 v1 = __floats2half2_rn(o[mi][2] * rh, o[mi][3] * rh);
        *(__half2*)&g_y[base + (size_t)(h0 + 8) * 32 * EDIM + r2] = v1;
    }
}

// ---------------------------------------------------------------------------
// K2: out = y @ W^T + bias over one chunk of M rows (R6/R11 body).
// ---------------------------------------------------------------------------
#define STAGE_BYTES 32768            // 16KB A + 16KB B per stage
#define GEMM_SMEM   65536

__global__ __launch_bounds__(256) void gemm_kernel(const float* __restrict__ bias,
                                                   float* __restrict__ out,
                                                   int mBase) {
    extern __shared__ __align__(1024) char smem[];
    const uint32_t sb = smem_u32(smem);
    const int tid  = threadIdx.x;
    const int warp = tid >> 5;
    const int lane = tid & 31;
    const int wm   = warp >> 2;      // 0..1
    const int wn   = warp & 3;       // 0..3
    const int blockM = mBase + blockIdx.x * 128;
    const int blockN = blockIdx.y * 128;

    const int lrow = tid >> 3;            // 0..31
    const int lcb  = (tid & 7) * 16;      // byte col in 128B row

    auto load_stage = [&](int s) {
        const int kt = s * 64;
        const uint32_t base = sb + (s & 1) * STAGE_BYTES;
        #pragma unroll
        for (int i = 0; i < 4; i++) {
            int row = lrow + i * 32;
            uint32_t o = SW128(row * 128 + lcb);
            cp16(base + o, &g_y[(size_t)(blockM + row) * 512 + kt + (lcb >> 1)]);
            cp16(base + 16384 + o, &g_W[(size_t)(blockN + row) * 512 + kt + (lcb >> 1)]);
        }
        CP_COMMIT();
    };

    float c[4][4][4];
    #pragma unroll
    for (int mi = 0; mi < 4; mi++)
        #pragma unroll
        for (int nj = 0; nj < 4; nj++)
            c[mi][nj][0] = c[mi][nj][1] = c[mi][nj][2] = c[mi][nj][3] = 0.f;

    load_stage(0);

    const int t  = lane & 15;
    const int hh = (lane >> 4) * 16;

    #pragma unroll 1
    for (int s = 0; s < 8; s++) {
        if (s + 1 < 8) { load_stage(s + 1); CP_WAIT(1); }
        else           { CP_WAIT(0); }
        __syncthreads();

        const uint32_t abase = sb + (s & 1) * STAGE_BYTES;
        const uint32_t bbase = abase + 16384;

        #pragma unroll
        for (int ks = 0; ks < 4; ks++) {
            uint32_t ra[4][4], rb[2][4];
            #pragma unroll
            for (int mi = 0; mi < 4; mi++) {
                uint32_t o = (wm * 64 + mi * 16 + t) * 128 + ks * 32 + hh;
                ldsm_x4(ra[mi], abase + SW128(o));
            }
            #pragma unroll
            for (int g = 0; g < 2; g++) {
                uint32_t o = (wn * 32 + g * 16 + t) * 128 + ks * 32 + hh;
                ldsm_x4(rb[g], bbase + SW128(o));   // non-trans: rows = n, k contiguous
            }
            #pragma unroll
            for (int mi = 0; mi < 4; mi++)
                #pragma unroll
                for (int nj = 0; nj < 4; nj++)
                    mma_16n8k16(c[mi][nj], ra[mi],
                                rb[nj >> 1][nj & 1], rb[nj >> 1][2 + (nj & 1)]);
        }
        __syncthreads();
    }

    const int q  = lane >> 2;
    const int r2 = (lane & 3) * 2;
    #pragma unroll
    for (int nj = 0; nj < 4; nj++) {
        const int col = blockN + wn * 32 + nj * 8 + r2;
        const float2 bv = *(const float2*)&bias[col];
        #pragma unroll
        for (int mi = 0; mi < 4; mi++) {
            const int row = blockM + wm * 64 + mi * 16 + q;
            float2 v0 = {c[mi][nj][0] + bv.x, c[mi][nj][1] + bv.y};
            float2 v1 = {c[mi][nj][2] + bv.x, c[mi][nj][3] + bv.y};
            *(float2*)&out[(size_t)row * 512 + col] = v0;
            *(float2*)&out[(size_t)(row + 8) * 512 + col] = v1;
        }
    }
}

// ---------------------------------------------------------------------------
// Stream/event pool, created at program load (before harness mem checkpoints).
// ---------------------------------------------------------------------------
struct StreamPool {
    cudaStream_t s2;
    cudaEvent_t evA[2];
    cudaEvent_t evG;
    StreamPool() {
        cudaStreamCreateWithFlags(&s2, cudaStreamNonBlocking);
        for (int i = 0; i < 2; i++)
            cudaEventCreateWithFlags(&evA[i], cudaEventDisableTiming);
        cudaEventCreateWithFlags(&evG, cudaEventDisableTiming);
    }
};
static StreamPool g_sp;

// ---------------------------------------------------------------------------
// 2 chunks: 3 batches then 5 batches. attn on stream 0, gemm on s2 gated by
// events. G0 (small) overlaps A1 (large); G1 runs at full width after attn.
// W converted inside A0 (before the first event fires).
// ---------------------------------------------------------------------------
extern "C" void kernel_launch(void* const* d_in, const int* in_sizes, int n_in,
                              void* d_out, int out_size) {
    const float* x     = (const float*)d_in[0];
    const float* theta = (const float*)d_in[1];
    const float* W     = (const float*)d_in[2];
    const float* bias  = (const float*)d_in[3];
    float* out = (float*)d_out;

    cudaFuncSetAttribute(gemm_kernel, cudaFuncAttributeMaxDynamicSharedMemorySize, GEMM_SMEM);

    // chunk 0: batches 0-2 (6144 tokens / rows)
    attn_kernel<<<768, 256, 0, 0>>>(x, theta, W, 0, 1);
    cudaEventRecord(g_sp.evA[0], 0);
    cudaStreamWaitEvent(g_sp.s2, g_sp.evA[0], 0);
    gemm_kernel<<<dim3(48, 4), 256, GEMM_SMEM, g_sp.s2>>>(bias, out, 0);

    // chunk 1: batches 3-7 (10240 tokens / rows)
    attn_kernel<<<1280, 256, 0, 0>>>(x, theta, W, 6144, 0);
    cudaEventRecord(g_sp.evA[1], 0);
    cudaStreamWaitEvent(g_sp.s2, g_sp.evA[1], 0);
    gemm_kernel<<<dim3(80, 4), 256, GEMM_SMEM, g_sp.s2>>>(bias, out, 6144);

    cudaEventRecord(g_sp.evG, g_sp.s2);
    cudaStreamWaitEvent(0, g_sp.evG, 0);
}

// round 15
// speedup vs baseline: 1.1149x; 1.1084x over previous
#include <cuda_runtime.h>
#include <cuda_fp16.h>
#include <cstdint>

#define TOKENS (8*2048)
#define EDIM 512

// Scratch: permuted attention output in fp16, W in fp16.
__device__ __half g_y[(size_t)TOKENS * EDIM];   // 16 MB
__device__ __half g_W[EDIM * EDIM];             // 512 KB

// ============================ helpers ======================================
__device__ __forceinline__ float ex2(float x) {
    float r; asm("ex2.approx.f32 %0, %1;" : "=f"(r) : "f"(x)); return r;
}
__device__ __forceinline__ uint32_t f22h2(float a, float b) {
    __half2 h = __floats2half2_rn(a, b);
    return *(uint32_t*)&h;
}
__device__ __forceinline__ float2 h2f2(uint32_t u) {
    return __half22float2(*(__half2*)&u);
}
__device__ __forceinline__ uint32_t smem_u32(const void* p) {
    uint32_t a;
    asm("{ .reg .u64 t; cvta.to.shared.u64 t, %1; cvt.u32.u64 %0, t; }" : "=r"(a) : "l"(p));
    return a;
}
__device__ __forceinline__ uint32_t movm(uint32_t s) {
    uint32_t d;
    asm volatile("movmatrix.sync.aligned.m8n8.trans.b16 %0, %1;" : "=r"(d) : "r"(s));
    return d;
}
__device__ __forceinline__ void mma_16n8k8(float* c, uint32_t a0, uint32_t a1, uint32_t b0) {
    asm volatile(
        "mma.sync.aligned.m16n8k8.row.col.f32.f16.f16.f32 "
        "{%0,%1,%2,%3}, {%4,%5}, {%6}, {%0,%1,%2,%3};"
        : "+f"(c[0]), "+f"(c[1]), "+f"(c[2]), "+f"(c[3])
        : "r"(a0), "r"(a1), "r"(b0));
}
__device__ __forceinline__ void mma_16n8k16(float* c, const uint32_t* a,
                                            uint32_t b0, uint32_t b1) {
    asm volatile(
        "mma.sync.aligned.m16n8k16.row.col.f32.f16.f16.f32 "
        "{%0,%1,%2,%3}, {%4,%5,%6,%7}, {%8,%9}, {%0,%1,%2,%3};"
        : "+f"(c[0]), "+f"(c[1]), "+f"(c[2]), "+f"(c[3])
        : "r"(a[0]), "r"(a[1]), "r"(a[2]), "r"(a[3]), "r"(b0), "r"(b1));
}
__device__ __forceinline__ void ldsm_x4(uint32_t* r, uint32_t addr) {
    asm volatile("ldmatrix.sync.aligned.m8n8.x4.shared.b16 {%0,%1,%2,%3}, [%4];"
        : "=r"(r[0]), "=r"(r[1]), "=r"(r[2]), "=r"(r[3]) : "r"(addr));
}
__device__ __forceinline__ void cp16(uint32_t saddr, const void* gptr) {
    asm volatile("cp.async.cg.shared.global [%0], [%1], 16;" :: "r"(saddr), "l"(gptr));
}
#define CP_COMMIT()  asm volatile("cp.async.commit_group;" ::: "memory")
#define CP_WAIT(n)   asm volatile("cp.async.wait_group %0;" :: "n"(n) : "memory")
#define SW128(o) ((o) ^ (((o) >> 3) & 0x70))
#define TRI(a, b) ((a) * ((a) - 1) / 2 + (b))     // a > b

// ---------------------------------------------------------------------------
// K1: per-token quantum attention (R11 symmetric-exp body, unchanged).
// ---------------------------------------------------------------------------
__global__ __launch_bounds__(256) void attn_kernel(const float* __restrict__ x,
                                                   const float* __restrict__ theta,
                                                   const float* __restrict__ W) {
    if (blockIdx.x < 128) {   // hidden W fp16 convert
        int t = blockIdx.x * 256 + threadIdx.x;
        float4 aq = *(const float4*)&W[(size_t)t * 8];
        float4 bq = *(const float4*)&W[(size_t)t * 8 + 4];
        __half2 h[4] = {__floats2half2_rn(aq.x, aq.y), __floats2half2_rn(aq.z, aq.w),
                        __floats2half2_rn(bq.x, bq.y), __floats2half2_rn(bq.z, bq.w)};
        *(uint4*)&g_W[(size_t)t * 8] = *(uint4*)h;
    }

    __shared__ __half sproj[8][512];        // [warp][h*8+d]
    __shared__ __half sprojT[8][8][72];     // [warp][d][h], pitch 72 halfs

    const int warp = threadIdx.x >> 5;
    const int lane = threadIdx.x & 31;
    const int token = blockIdx.x * 8 + warp;
    const float* xt = x + (size_t)token * EDIM;

    const float tv = __ldg(&theta[lane & 7]);
    #pragma unroll
    for (int i = 0; i < 16; i++) {
        int idx = lane + 32 * i;
        __half c = __float2half(__cosf(xt[idx] + tv));
        sproj[warp][idx] = c;
        sprojT[warp][idx & 7][idx >> 3] = c;
    }
    __syncwarp();

    const int q  = lane >> 2;
    const int r2 = (lane & 3) * 2;
    const float C2 = 0.51006973f;    // log2(e)/sqrt(8)

    uint32_t aA[4][2];
    #pragma unroll
    for (int mi = 0; mi < 4; mi++) {
        float2 lo = h2f2(*(const uint32_t*)&sproj[warp][(16 * mi + q) * 8 + r2]);
        float2 hi = h2f2(*(const uint32_t*)&sproj[warp][(16 * mi + q + 8) * 8 + r2]);
        aA[mi][0] = f22h2(lo.x * C2, lo.y * C2);
        aA[mi][1] = f22h2(hi.x * C2, hi.y * C2);
    }

    float o[4][4];
    float lsl[4], lsh[4];
    #pragma unroll
    for (int mi = 0; mi < 4; mi++) {
        o[mi][0] = o[mi][1] = o[mi][2] = o[mi][3] = 0.f;
        lsl[mi] = lsh[mi] = 0.f;
    }

    uint32_t Psrc[28];      // retained lower-tri halves E(a,b), a>b

    #pragma unroll
    for (int nj = 0; nj < 8; nj++) {
        uint32_t bS = *(const uint32_t*)&sproj[warp][(8 * nj + q) * 8 + r2];
        uint32_t bO = *(const uint32_t*)&sprojT[warp][q][8 * nj + r2];
        uint32_t eh[8];

        #pragma unroll
        for (int a = 0; a < nj; a++) {
            eh[a] = movm(Psrc[TRI(nj, a)]);
            float2 f = h2f2(eh[a]);
            if (a & 1) lsh[a >> 1] += f.x + f.y;
            else       lsl[a >> 1] += f.x + f.y;
        }
        #pragma unroll
        for (int mi = 0; mi < 4; mi++) {
            if (mi >= (nj >> 1)) {
                float c[4] = {0.f, 0.f, 0.f, 0.f};
                mma_16n8k8(c, aA[mi][0], aA[mi][1], bS);
                const int a0 = 2 * mi, a1 = 2 * mi + 1;
                if (a0 >= nj) {
                    float p0 = ex2(c[0]), p1 = ex2(c[1]);
                    lsl[mi] += p0 + p1;
                    eh[a0] = f22h2(p0, p1);
                    if (a0 > nj) Psrc[TRI(a0, nj)] = eh[a0];
                }
                {
                    float p2 = ex2(c[2]), p3 = ex2(c[3]);
                    lsh[mi] += p2 + p3;
                    eh[a1] = f22h2(p2, p3);
                    if (a1 > nj) Psrc[TRI(a1, nj)] = eh[a1];
                }
            }
        }
        #pragma unroll
        for (int mi = 0; mi < 4; mi++)
            mma_16n8k8(o[mi], eh[2 * mi], eh[2 * mi + 1], bO);
    }

    #pragma unroll
    for (int mi = 0; mi < 4; mi++) {
        lsl[mi] += __shfl_xor_sync(0xffffffffu, lsl[mi], 1);
        lsl[mi] += __shfl_xor_sync(0xffffffffu, lsl[mi], 2);
        lsh[mi] += __shfl_xor_sync(0xffffffffu, lsh[mi], 1);
        lsh[mi] += __shfl_xor_sync(0xffffffffu, lsh[mi], 2);
    }

    const int b = token >> 11;
    const int s = token & 2047;
    const size_t base = ((size_t)b * 2048 + (s >> 6)) * EDIM + (size_t)(s & 63) * 8;

    #pragma unroll
    for (int mi = 0; mi < 4; mi++) {
        float rl = __frcp_rn(lsl[mi]);
        float rh = __frcp_rn(lsh[mi]);
        int h0 = 16 * mi + q;
        __half2 v0 = __floats2half2_rn(o[mi][0] * rl, o[mi][1] * rl);
        *(__half2*)&g_y[base + (size_t)h0 * 32 * EDIM + r2] = v0;
        __half2 v1 = __floats2half2_rn(o[mi][2] * rh, o[mi][3] * rh);
        *(__half2*)&g_y[base + (size_t)(h0 + 8) * 32 * EDIM + r2] = v1;
    }
}

// ---------------------------------------------------------------------------
// K2: out = y @ W^T + bias.  M=16384, N=512, K=512.
// OCCUPANCY RETILE: BM=128 BN=64 BK=64; warp tile 32x32 (32 accum regs),
// __launch_bounds__(256,3) -> 3 CTAs/SM = 6 warps/SMSP (HMMA latency hiding).
// mma.sync.m16n8k16 + ldmatrix (non-trans) + SW128 + cp.async 2-stage.
// ---------------------------------------------------------------------------
#define A_BYTES     16384                 // 128 rows x 128B
#define B_BYTES     8192                  // 64 rows x 128B
#define STAGE_BYTES (A_BYTES + B_BYTES)   // 24KB
#define GEMM_SMEM   (2 * STAGE_BYTES)     // 48KB

__global__ __launch_bounds__(256, 3) void gemm_kernel(const float* __restrict__ bias,
                                                      float* __restrict__ out) {
    extern __shared__ __align__(1024) char smem[];
    const uint32_t sb = smem_u32(smem);
    const int tid  = threadIdx.x;
    const int warp = tid >> 5;
    const int lane = tid & 31;
    const int wm   = warp >> 1;      // 0..3  (32 rows each)
    const int wn   = warp & 1;       // 0..1  (32 cols each)
    const int blockM = blockIdx.x * 128;
    const int blockN = blockIdx.y * 64;

    const int lrow = tid >> 3;            // 0..31
    const int lcb  = (tid & 7) * 16;      // byte col in 128B row

    auto load_stage = [&](int s) {
        const int kt = s * 64;
        const uint32_t base = sb + (s & 1) * STAGE_BYTES;
        #pragma unroll
        for (int i = 0; i < 4; i++) {     // A: 128 rows
            int row = lrow + i * 32;
            cp16(base + SW128(row * 128 + lcb),
                 &g_y[(size_t)(blockM + row) * 512 + kt + (lcb >> 1)]);
        }
        #pragma unroll
        for (int i = 0; i < 2; i++) {     // B: 64 rows
            int row = lrow + i * 32;
            cp16(base + A_BYTES + SW128(row * 128 + lcb),
                 &g_W[(size_t)(blockN + row) * 512 + kt + (lcb >> 1)]);
        }
        CP_COMMIT();
    };

    float c[2][4][4];
    #pragma unroll
    for (int mi = 0; mi < 2; mi++)
        #pragma unroll
        for (int nj = 0; nj < 4; nj++)
            c[mi][nj][0] = c[mi][nj][1] = c[mi][nj][2] = c[mi][nj][3] = 0.f;

    load_stage(0);

    const int t  = lane & 15;        // row within 16-row ldmatrix tile
    const int hh = (lane >> 4) * 16; // 16B k-half select

    #pragma unroll 1
    for (int s = 0; s < 8; s++) {
        if (s + 1 < 8) { load_stage(s + 1); CP_WAIT(1); }
        else           { CP_WAIT(0); }
        __syncthreads();

        const uint32_t abase = sb + (s & 1) * STAGE_BYTES;
        const uint32_t bbase = abase + A_BYTES;

        #pragma unroll
        for (int ks = 0; ks < 4; ks++) {
            uint32_t ra[2][4], rb[2][4];
            #pragma unroll
            for (int mi = 0; mi < 2; mi++) {
                uint32_t o = (wm * 32 + mi * 16 + t) * 128 + ks * 32 + hh;
                ldsm_x4(ra[mi], abase + SW128(o));
            }
            #pragma unroll
            for (int g = 0; g < 2; g++) {
                uint32_t o = (wn * 32 + g * 16 + t) * 128 + ks * 32 + hh;
                ldsm_x4(rb[g], bbase + SW128(o));   // non-trans: rows = n, k contiguous
            }
            #pragma unroll
            for (int mi = 0; mi < 2; mi++)
                #pragma unroll
                for (int nj = 0; nj < 4; nj++)
                    mma_16n8k16(c[mi][nj], ra[mi],
                                rb[nj >> 1][nj & 1], rb[nj >> 1][2 + (nj & 1)]);
        }
        __syncthreads();
    }

    // epilogue: bias + direct float2 stores
    const int q  = lane >> 2;
    const int r2 = (lane & 3) * 2;
    #pragma unroll
    for (int nj = 0; nj < 4; nj++) {
        const int col = blockN + wn * 32 + nj * 8 + r2;
        const float2 bv = *(const float2*)&bias[col];
        #pragma unroll
        for (int mi = 0; mi < 2; mi++) {
            const int row = blockM + wm * 32 + mi * 16 + q;
            float2 v0 = {c[mi][nj][0] + bv.x, c[mi][nj][1] + bv.y};
            float2 v1 = {c[mi][nj][2] + bv.x, c[mi][nj][3] + bv.y};
            *(float2*)&out[(size_t)row * 512 + col] = v0;
            *(float2*)&out[(size_t)(row + 8) * 512 + col] = v1;
        }
    }
}

// ---------------------------------------------------------------------------
extern "C" void kernel_launch(void* const* d_in, const int* in_sizes, int n_in,
                              void* d_out, int out_size) {
    const float* x     = (const float*)d_in[0];
    const float* theta = (const float*)d_in[1];
    const float* W     = (const float*)d_in[2];
    const float* bias  = (const float*)d_in[3];
    float* out = (float*)d_out;

    cudaFuncSetAttribute(gemm_kernel, cudaFuncAttributeMaxDynamicSharedMemorySize, GEMM_SMEM);
    attn_kernel<<<TOKENS / 8, 256>>>(x, theta, W);
    gemm_kernel<<<dim3(16384 / 128, 512 / 64), 256, GEMM_SMEM>>>(bias, out);
}